// round 1
// baseline (speedup 1.0000x reference)
#include <cuda_runtime.h>

// LDPC belief propagation, (7,4) Hamming code, 5 iterations, B=262144.
//
// Reference math per batch element b (llr = 7 floats):
//   rows: r0={0,2,4,6}, r1={1,2,5,6}, r2={3,4,5,6}
//   iterate 5x:
//     t[c][v]   = tanh((llr[v] + m_c2v[c][v]) / 2)
//     m_new[c][v] = prod_{k in row c, k != v} t[c][k]     (phi == identity, eps-div ~ leave-one-out)
//     total[v]  = llr[v] + sum_c m_new[c][v] + (3 - deg(v))   (non-edges contribute phi(1)=1)
//     m_c2v'    = (llr[v] + total[v]) - m_new[c][v]  per edge
//   output[v] = 2 * (llr[v] + total_final[v])
//
// Everything is kept scaled by log2(e) so that
//   tanh(x/2) = (1 - a) / (1 + a),  a = exp2(M - Tl)
// costs exactly one SUB + one EX2 + one RCP + 3 FMA-class ops per edge.

#define L2E 1.4426950408889634f

__device__ __forceinline__ float fast_ex2(float x) {
    float y;
    asm("ex2.approx.ftz.f32 %0, %1;" : "=f"(y) : "f"(x));
    return y;
}

__device__ __forceinline__ float fast_rcp(float x) {
    float y;
    asm("rcp.approx.ftz.f32 %0, %1;" : "=f"(y) : "f"(x));
    return y;
}

// t = tanh(x/2) where (M - Tl) == -x * log2(e)
__device__ __forceinline__ float edge_t(float M, float Tl) {
    float a = fast_ex2(M - Tl);
    return (1.0f - a) * fast_rcp(1.0f + a);
}

__global__ __launch_bounds__(256)
void ldpc_bp_kernel(const float* __restrict__ llr, float* __restrict__ out, int B) {
    int b = blockIdx.x * blockDim.x + threadIdx.x;
    if (b >= B) return;

    const float* p = llr + (size_t)b * 7;

    // scaled llr:  l = llr * log2(e)
    float l0 = p[0] * L2E, l1 = p[1] * L2E, l2 = p[2] * L2E, l3 = p[3] * L2E;
    float l4 = p[4] * L2E, l5 = p[5] * L2E, l6 = p[6] * L2E;

    // base[v] = 2*l[v] + (3 - deg(v)) * log2(e); deg = {1,1,2,1,2,2,3}
    const float base0 = 2.0f * l0 + 2.0f * L2E;
    const float base1 = 2.0f * l1 + 2.0f * L2E;
    const float base2 = 2.0f * l2 + 1.0f * L2E;
    const float base3 = 2.0f * l3 + 2.0f * L2E;
    const float base4 = 2.0f * l4 + 1.0f * L2E;
    const float base5 = 2.0f * l5 + 1.0f * L2E;
    const float base6 = 2.0f * l6;

    // Tl[v] = (llr[v] + total_prev[v]) * log2(e); iter 1 has m_c2v = 0 -> Tl = l
    float T0 = l0, T1 = l1, T2 = l2, T3 = l3, T4 = l4, T5 = l5, T6 = l6;

    // scaled messages M = m_new * log2(e), per edge
    float m00 = 0.f, m01 = 0.f, m02 = 0.f, m03 = 0.f;  // row0: v0,v2,v4,v6
    float m10 = 0.f, m11 = 0.f, m12 = 0.f, m13 = 0.f;  // row1: v1,v2,v5,v6
    float m20 = 0.f, m21 = 0.f, m22 = 0.f, m23 = 0.f;  // row2: v3,v4,v5,v6

#pragma unroll
    for (int it = 0; it < 5; ++it) {
        // ---- row 0: variables 0,2,4,6 ----
        {
            float t0 = edge_t(m00, T0);
            float t1 = edge_t(m01, T2);
            float t2 = edge_t(m02, T4);
            float t3 = edge_t(m03, T6);
            float pa = t0 * t1, pb = t2 * t3;
            float paL = pa * L2E, pbL = pb * L2E;
            m00 = t1 * pbL;   // (t1*t2*t3) * L2E
            m01 = t0 * pbL;
            m02 = paL * t3;
            m03 = paL * t2;
        }
        // ---- row 1: variables 1,2,5,6 ----
        {
            float t0 = edge_t(m10, T1);
            float t1 = edge_t(m11, T2);
            float t2 = edge_t(m12, T5);
            float t3 = edge_t(m13, T6);
            float pa = t0 * t1, pb = t2 * t3;
            float paL = pa * L2E, pbL = pb * L2E;
            m10 = t1 * pbL;
            m11 = t0 * pbL;
            m12 = paL * t3;
            m13 = paL * t2;
        }
        // ---- row 2: variables 3,4,5,6 ----
        {
            float t0 = edge_t(m20, T3);
            float t1 = edge_t(m21, T4);
            float t2 = edge_t(m22, T5);
            float t3 = edge_t(m23, T6);
            float pa = t0 * t1, pb = t2 * t3;
            float paL = pa * L2E, pbL = pb * L2E;
            m20 = t1 * pbL;
            m21 = t0 * pbL;
            m22 = paL * t3;
            m23 = paL * t2;
        }
        // ---- Tl update: Tl' = 2*l + const + sum_c M_new ----
        T0 = base0 + m00;
        T1 = base1 + m10;
        T2 = base2 + (m01 + m11);
        T3 = base3 + m20;
        T4 = base4 + (m02 + m21);
        T5 = base5 + (m12 + m22);
        T6 = base6 + ((m03 + m13) + m23);
    }

    // output = 2*(llr + total) = (2 / log2(e)) * Tl_final = 2*ln(2) * Tl_final
    const float OUTSCALE = 1.3862943611198906f;  // 2*ln(2)
    float* q = out + (size_t)b * 7;
    q[0] = T0 * OUTSCALE;
    q[1] = T1 * OUTSCALE;
    q[2] = T2 * OUTSCALE;
    q[3] = T3 * OUTSCALE;
    q[4] = T4 * OUTSCALE;
    q[5] = T5 * OUTSCALE;
    q[6] = T6 * OUTSCALE;
}

extern "C" void kernel_launch(void* const* d_in, const int* in_sizes, int n_in,
                              void* d_out, int out_size) {
    const float* llr = (const float*)d_in[0];
    float* out = (float*)d_out;
    int B = in_sizes[0] / 7;  // 262144

    const int threads = 256;
    int blocks = (B + threads - 1) / threads;
    ldpc_bp_kernel<<<blocks, threads>>>(llr, out, B);
}

// round 3
// speedup vs baseline: 1.2094x; 1.2094x over previous
#include <cuda_runtime.h>

// LDPC BP, (7,4) Hamming, 5 iterations, B=262144.
//
// Half-domain formulation:
//   Th[v]  = (llr[v] + total[v]) / 2        (state per variable)
//   mh     = m_new / 2                      (state per edge)
//   edge:  t = tanh(Th - mh)                <- ONE MUFU.TANH (tanh.approx.f32)
//   row:   leave-one-out products of t, folded x0.5 -> new mh
//   Th'    = llr[v] + (3-deg(v))/2 + sum_c mh[c][v]
//   out[v] = llr + sum_c m_v2c = 2*(llr+total) = 4 * Th_final[v]   (fixed scale)
//
// rows: r0={0,2,4,6}, r1={1,2,5,6}, r2={3,4,5,6}; deg = {1,1,2,1,2,2,3}

__device__ __forceinline__ float fast_tanh(float x) {
    float y;
    asm("tanh.approx.f32 %0, %1;" : "=f"(y) : "f"(x));
    return y;
}

__global__ __launch_bounds__(256)
void ldpc_bp_kernel(const float* __restrict__ llr, float* __restrict__ out, int B) {
    int b = blockIdx.x * blockDim.x + threadIdx.x;
    if (b >= B) return;

    const float* p = llr + (size_t)b * 7;
    float l0 = p[0], l1 = p[1], l2 = p[2], l3 = p[3], l4 = p[4], l5 = p[5], l6 = p[6];

    // base[v] = llr[v] + (3 - deg(v))/2
    const float base0 = l0 + 1.0f;
    const float base1 = l1 + 1.0f;
    const float base2 = l2 + 0.5f;
    const float base3 = l3 + 1.0f;
    const float base4 = l4 + 0.5f;
    const float base5 = l5 + 0.5f;
    const float base6 = l6;

    // First-iteration edge arg is llr/2 (messages start at 0) -> Th = llr/2.
    float T0 = 0.5f * l0, T1 = 0.5f * l1, T2 = 0.5f * l2, T3 = 0.5f * l3;
    float T4 = 0.5f * l4, T5 = 0.5f * l5, T6 = 0.5f * l6;

    // half-messages mh = m_new/2 per edge
    float m00 = 0.f, m01 = 0.f, m02 = 0.f, m03 = 0.f;  // row0: v0,v2,v4,v6
    float m10 = 0.f, m11 = 0.f, m12 = 0.f, m13 = 0.f;  // row1: v1,v2,v5,v6
    float m20 = 0.f, m21 = 0.f, m22 = 0.f, m23 = 0.f;  // row2: v3,v4,v5,v6

#pragma unroll
    for (int it = 0; it < 5; ++it) {
        // ---- row 0: v0,v2,v4,v6 ----
        {
            float t0 = fast_tanh(T0 - m00);
            float t1 = fast_tanh(T2 - m01);
            float t2 = fast_tanh(T4 - m02);
            float t3 = fast_tanh(T6 - m03);
            float pa = t0 * t1, pb = t2 * t3;
            float pah = 0.5f * pa, pbh = 0.5f * pb;
            m00 = t1 * pbh;   // 0.5 * t1*t2*t3
            m01 = t0 * pbh;
            m02 = pah * t3;
            m03 = pah * t2;
        }
        // ---- row 1: v1,v2,v5,v6 ----
        {
            float t0 = fast_tanh(T1 - m10);
            float t1 = fast_tanh(T2 - m11);
            float t2 = fast_tanh(T5 - m12);
            float t3 = fast_tanh(T6 - m13);
            float pa = t0 * t1, pb = t2 * t3;
            float pah = 0.5f * pa, pbh = 0.5f * pb;
            m10 = t1 * pbh;
            m11 = t0 * pbh;
            m12 = pah * t3;
            m13 = pah * t2;
        }
        // ---- row 2: v3,v4,v5,v6 ----
        {
            float t0 = fast_tanh(T3 - m20);
            float t1 = fast_tanh(T4 - m21);
            float t2 = fast_tanh(T5 - m22);
            float t3 = fast_tanh(T6 - m23);
            float pa = t0 * t1, pb = t2 * t3;
            float pah = 0.5f * pa, pbh = 0.5f * pb;
            m20 = t1 * pbh;
            m21 = t0 * pbh;
            m22 = pah * t3;
            m23 = pah * t2;
        }
        // ---- Th update ----
        T0 = base0 + m00;
        T1 = base1 + m10;
        T2 = base2 + (m01 + m11);
        T3 = base3 + m20;
        T4 = base4 + (m02 + m21);
        T5 = base5 + (m12 + m22);
        T6 = base6 + ((m03 + m13) + m23);
    }

    // out = llr + sum_c m_v2c = 2*(llr + total) = 4 * Th_final
    const float OUT = 4.0f;
    float* q = out + (size_t)b * 7;
    q[0] = OUT * T0;
    q[1] = OUT * T1;
    q[2] = OUT * T2;
    q[3] = OUT * T3;
    q[4] = OUT * T4;
    q[5] = OUT * T5;
    q[6] = OUT * T6;
}

extern "C" void kernel_launch(void* const* d_in, const int* in_sizes, int n_in,
                              void* d_out, int out_size) {
    const float* llr = (const float*)d_in[0];
    float* out = (float*)d_out;
    int B = in_sizes[0] / 7;  // 262144

    const int threads = 256;
    int blocks = (B + threads - 1) / threads;
    ldpc_bp_kernel<<<blocks, threads>>>(llr, out, B);
}

// round 4
// speedup vs baseline: 1.2316x; 1.0184x over previous
#include <cuda_runtime.h>
#include <cuda_fp16.h>

// LDPC BP, (7,4) Hamming, 5 iterations, B=262144. MUFU.TANH-bound kernel.
//
// Half-domain: Th=(llr+total)/2, mh=m_new/2, t=tanh(Th-mh), out=4*Th_final.
// rows: r0={0,2,4,6}, r1={1,2,5,6}, r2={3,4,5,6}; deg={1,1,2,1,2,2,3}
//
// tanh reductions:
//  * deg-1 vars (v0,v1,v3): edge arg == llr+1, constant for iters>=2 (3 tanh once)
//  * iter 1: args = llr_v/2, shared per variable (7 tanh, not 12)
//  * iters 1-3 use tanh.approx.f16x2 (2 edges / MUFU slot); iters 4-5 + consts f32

__device__ __forceinline__ float tanhf32(float x) {
    float y;
    asm("tanh.approx.f32 %0, %1;" : "=f"(y) : "f"(x));
    return y;
}

// ta = tanh(a), tb = tanh(b) via one f16x2 MUFU op
__device__ __forceinline__ void tanh_pair(float a, float b, float& ta, float& tb) {
    asm("{\n"
        " .reg .b32 u;\n"
        " .reg .b16 lo, hi;\n"
        " cvt.rn.f16x2.f32 u, %3, %2;\n"   // hi<-b, lo<-a
        " tanh.approx.f16x2 u, u;\n"
        " mov.b32 {lo, hi}, u;\n"
        " cvt.f32.f16 %0, lo;\n"
        " cvt.f32.f16 %1, hi;\n"
        "}" : "=f"(ta), "=f"(tb) : "f"(a), "f"(b));
}

__global__ __launch_bounds__(256)
void ldpc_bp_kernel(const float* __restrict__ llr, float* __restrict__ out, int B) {
    int b = blockIdx.x * blockDim.x + threadIdx.x;
    if (b >= B) return;

    const float* p = llr + (size_t)b * 7;
    float l0 = p[0], l1 = p[1], l2 = p[2], l3 = p[3], l4 = p[4], l5 = p[5], l6 = p[6];

    // constant half-scaled t for deg-1 edges, valid for iterations >= 2
    float c0h = 0.5f * tanhf32(l0 + 1.0f);
    float c1h = 0.5f * tanhf32(l1 + 1.0f);
    float c3h = 0.5f * tanhf32(l3 + 1.0f);

    const float base2 = l2 + 0.5f;
    const float base4 = l4 + 0.5f;
    const float base5 = l5 + 0.5f;
    const float base6 = l6;

    float T2, T4, T5, T6;
    float m01, m02, m03;   // row0 msgs to v2,v4,v6 (half)
    float m11, m12, m13;   // row1 msgs to v2,v5,v6
    float m21, m22, m23;   // row2 msgs to v4,v5,v6

    // ---------- iteration 1: all edge args = l_v/2, shared per variable ----------
    {
        float tv0, tv1, tv2, tv3, tv4, tv5, tv6;
        tanh_pair(0.5f * l0, 0.5f * l1, tv0, tv1);
        tanh_pair(0.5f * l2, 0.5f * l3, tv2, tv3);
        tanh_pair(0.5f * l4, 0.5f * l5, tv4, tv5);
        tv6 = tanhf32(0.5f * l6);

        float t0h = 0.5f * tv0, t1h = 0.5f * tv1, t3h = 0.5f * tv3;
        float pb0 = tv4 * tv6, pa0 = t0h * tv2;
        m01 = t0h * pb0;  m02 = pa0 * tv6;  m03 = pa0 * tv4;
        float pb1 = tv5 * tv6, pa1 = t1h * tv2;
        m11 = t1h * pb1;  m12 = pa1 * tv6;  m13 = pa1 * tv5;
        float pb2 = tv5 * tv6, pa2 = t3h * tv4;
        m21 = t3h * pb2;  m22 = pa2 * tv6;  m23 = pa2 * tv5;

        T2 = base2 + (m01 + m11);
        T4 = base4 + (m02 + m21);
        T5 = base5 + (m12 + m22);
        T6 = base6 + ((m03 + m13) + m23);
    }

    // ---------- iterations 2,3 (f16x2 tanh) ----------
#pragma unroll
    for (int it = 0; it < 2; ++it) {
        float a01 = T2 - m01, a02 = T4 - m02, a03 = T6 - m03;
        float a11 = T2 - m11, a12 = T5 - m12, a13 = T6 - m13;
        float a21 = T4 - m21, a22 = T5 - m22, a23 = T6 - m23;
        float t01, t02, t03, t11, t12, t13, t21, t22, t23;
        tanh_pair(a01, a02, t01, t02);
        tanh_pair(a03, a11, t03, t11);
        tanh_pair(a12, a13, t12, t13);
        tanh_pair(a21, a22, t21, t22);
        t23 = tanhf32(a23);

        float pb0 = t02 * t03, pa0 = c0h * t01;
        m01 = c0h * pb0;  m02 = pa0 * t03;  m03 = pa0 * t02;
        float pb1 = t12 * t13, pa1 = c1h * t11;
        m11 = c1h * pb1;  m12 = pa1 * t13;  m13 = pa1 * t12;
        float pb2 = t22 * t23, pa2 = c3h * t21;
        m21 = c3h * pb2;  m22 = pa2 * t23;  m23 = pa2 * t22;

        T2 = base2 + (m01 + m11);
        T4 = base4 + (m02 + m21);
        T5 = base5 + (m12 + m22);
        T6 = base6 + ((m03 + m13) + m23);
    }

    // ---------- iteration 4 (f32 tanh) ----------
    {
        float t01 = tanhf32(T2 - m01), t02 = tanhf32(T4 - m02), t03 = tanhf32(T6 - m03);
        float t11 = tanhf32(T2 - m11), t12 = tanhf32(T5 - m12), t13 = tanhf32(T6 - m13);
        float t21 = tanhf32(T4 - m21), t22 = tanhf32(T5 - m22), t23 = tanhf32(T6 - m23);

        float pb0 = t02 * t03, pa0 = c0h * t01;
        m01 = c0h * pb0;  m02 = pa0 * t03;  m03 = pa0 * t02;
        float pb1 = t12 * t13, pa1 = c1h * t11;
        m11 = c1h * pb1;  m12 = pa1 * t13;  m13 = pa1 * t12;
        float pb2 = t22 * t23, pa2 = c3h * t21;
        m21 = c3h * pb2;  m22 = pa2 * t23;  m23 = pa2 * t22;

        T2 = base2 + (m01 + m11);
        T4 = base4 + (m02 + m21);
        T5 = base5 + (m12 + m22);
        T6 = base6 + ((m03 + m13) + m23);
    }

    // ---------- iteration 5 (f32 tanh, also deg-1 messages for outputs) ----------
    float m00, m10, m20;
    {
        float t01 = tanhf32(T2 - m01), t02 = tanhf32(T4 - m02), t03 = tanhf32(T6 - m03);
        float t11 = tanhf32(T2 - m11), t12 = tanhf32(T5 - m12), t13 = tanhf32(T6 - m13);
        float t21 = tanhf32(T4 - m21), t22 = tanhf32(T5 - m22), t23 = tanhf32(T6 - m23);

        float pb0 = t02 * t03, pa0 = c0h * t01;
        m01 = c0h * pb0;  m02 = pa0 * t03;  m03 = pa0 * t02;
        m00 = t01 * (0.5f * pb0);
        float pb1 = t12 * t13, pa1 = c1h * t11;
        m11 = c1h * pb1;  m12 = pa1 * t13;  m13 = pa1 * t12;
        m10 = t11 * (0.5f * pb1);
        float pb2 = t22 * t23, pa2 = c3h * t21;
        m21 = c3h * pb2;  m22 = pa2 * t23;  m23 = pa2 * t22;
        m20 = t21 * (0.5f * pb2);

        T2 = base2 + (m01 + m11);
        T4 = base4 + (m02 + m21);
        T5 = base5 + (m12 + m22);
        T6 = base6 + ((m03 + m13) + m23);
    }

    float* q = out + (size_t)b * 7;
    q[0] = 4.0f * ((l0 + 1.0f) + m00);
    q[1] = 4.0f * ((l1 + 1.0f) + m10);
    q[2] = 4.0f * T2;
    q[3] = 4.0f * ((l3 + 1.0f) + m20);
    q[4] = 4.0f * T4;
    q[5] = 4.0f * T5;
    q[6] = 4.0f * T6;
}

extern "C" void kernel_launch(void* const* d_in, const int* in_sizes, int n_in,
                              void* d_out, int out_size) {
    const float* llr = (const float*)d_in[0];
    float* out = (float*)d_out;
    int B = in_sizes[0] / 7;  // 262144

    const int threads = 256;
    int blocks = (B + threads - 1) / threads;
    ldpc_bp_kernel<<<blocks, threads>>>(llr, out, B);
}